// round 3
// baseline (speedup 1.0000x reference)
#include <cuda_runtime.h>
#include <math.h>

// Problem constants (fixed by the dataset)
#define NN 50000      // nodes
#define EE 500000     // edges
#define DM 256        // d_model
#define NH 8          // heads
#define DK 32         // d_k

// ---------------------------------------------------------------------------
// Scratch (device globals — no runtime allocation allowed)
// ---------------------------------------------------------------------------
__device__ float g_q[(size_t)NN * DM];
__device__ float g_k[(size_t)NN * DM];
__device__ float g_v[(size_t)NN * DM];
__device__ float g_mid[(size_t)NN * DM];
__device__ int   g_cnt[NN];
__device__ int   g_off[NN + 1];
__device__ int   g_cur[NN];
__device__ int   g_src[EE];
__device__ int   g_is64;   // 1 if edges buffer is int64, 0 if int32

// ---------------------------------------------------------------------------
// Edge index dtype detection: jax may have canonicalized int64 -> int32.
// If the data is little-endian int64 with values in [0, 50000), every odd
// 32-bit word (high half) is zero. Sample 256 odd words; all-zero => int64.
// ---------------------------------------------------------------------------
__global__ void detect_kernel(const int* __restrict__ raw) {
    __shared__ int nz;
    if (threadIdx.x == 0) nz = 0;
    __syncthreads();
    int v = raw[2 * threadIdx.x + 1];
    if (v != 0) atomicAdd(&nz, 1);
    __syncthreads();
    if (threadIdx.x == 0) g_is64 = (nz == 0) ? 1 : 0;
}

__device__ __forceinline__ int load_edge(const void* edges, int idx) {
    if (g_is64) return (int)((const long long*)edges)[idx];
    return ((const int*)edges)[idx];
}

// ---------------------------------------------------------------------------
// SGEMM (NT): C[M,256] = X[M,256] @ W[256,256]^T + bias
// BM=BN=128, BK=8, 256 threads, 8x8 micro-tile per thread.
// ---------------------------------------------------------------------------
__global__ __launch_bounds__(256)
void sgemm_nt(const float* __restrict__ X, const float* __restrict__ W,
              const float* __restrict__ bias, float* __restrict__ C, int M) {
    __shared__ float As[8][128];
    __shared__ float Bs[8][128];

    const int tid = threadIdx.x;
    const int tx  = tid & 15;     // 0..15 -> 8 output cols each
    const int ty  = tid >> 4;     // 0..15 -> 8 output rows each
    const int rowBase = blockIdx.x * 128;
    const int colBase = blockIdx.y * 128;

    const int lr = tid >> 1;          // 0..127  tile row / weight row
    const int lk = (tid & 1) * 4;     // 0 or 4  k offset within BK

    float acc[8][8];
#pragma unroll
    for (int i = 0; i < 8; i++)
#pragma unroll
        for (int j = 0; j < 8; j++) acc[i][j] = 0.f;

    const int gr = rowBase + lr;
    const bool rok = (gr < M);
    const float* Xp = X + (size_t)gr * DM + lk;
    const float* Wp = W + (size_t)(colBase + lr) * DM + lk;

    for (int k0 = 0; k0 < DM; k0 += 8) {
        float4 a4 = rok ? *(const float4*)(Xp + k0) : make_float4(0.f, 0.f, 0.f, 0.f);
        float4 b4 = *(const float4*)(Wp + k0);
        As[lk + 0][lr] = a4.x; As[lk + 1][lr] = a4.y;
        As[lk + 2][lr] = a4.z; As[lk + 3][lr] = a4.w;
        Bs[lk + 0][lr] = b4.x; Bs[lk + 1][lr] = b4.y;
        Bs[lk + 2][lr] = b4.z; Bs[lk + 3][lr] = b4.w;
        __syncthreads();

#pragma unroll
        for (int kk = 0; kk < 8; kk++) {
            float a[8], b[8];
            *(float4*)&a[0] = *(const float4*)&As[kk][ty * 8];
            *(float4*)&a[4] = *(const float4*)&As[kk][ty * 8 + 4];
            *(float4*)&b[0] = *(const float4*)&Bs[kk][tx * 8];
            *(float4*)&b[4] = *(const float4*)&Bs[kk][tx * 8 + 4];
#pragma unroll
            for (int i = 0; i < 8; i++)
#pragma unroll
                for (int j = 0; j < 8; j++)
                    acc[i][j] += a[i] * b[j];
        }
        __syncthreads();
    }

    float bv[8];
#pragma unroll
    for (int j = 0; j < 8; j++) bv[j] = bias[colBase + tx * 8 + j];

#pragma unroll
    for (int i = 0; i < 8; i++) {
        int r = rowBase + ty * 8 + i;
        if (r < M) {
            float* Cp = C + (size_t)r * DM + colBase + tx * 8;
            float4 o0, o1;
            o0.x = acc[i][0] + bv[0]; o0.y = acc[i][1] + bv[1];
            o0.z = acc[i][2] + bv[2]; o0.w = acc[i][3] + bv[3];
            o1.x = acc[i][4] + bv[4]; o1.y = acc[i][5] + bv[5];
            o1.z = acc[i][6] + bv[6]; o1.w = acc[i][7] + bv[7];
            *(float4*)(Cp + 0) = o0;
            *(float4*)(Cp + 4) = o1;
        }
    }
}

// ---------------------------------------------------------------------------
// CSR build: histogram -> exclusive scan -> fill (sorted src per dst segment)
// ---------------------------------------------------------------------------
__global__ void zero_kernel(int* __restrict__ p, int n) {
    int i = blockIdx.x * blockDim.x + threadIdx.x;
    if (i < n) p[i] = 0;
}

__global__ void degree_kernel(const void* __restrict__ edges, int E,
                              int* __restrict__ cnt) {
    int e = blockIdx.x * blockDim.x + threadIdx.x;
    if (e < E) {
        int dst = load_edge(edges, e);          // edges[0][e]
        atomicAdd(&cnt[dst], 1);
    }
}

// Single-block exclusive scan over N counts (warp-shuffle based).
__global__ __launch_bounds__(1024)
void scan_kernel(const int* __restrict__ cnt, int* __restrict__ off, int N) {
    __shared__ int wsum[32];
    __shared__ int carry;
    const int lane = threadIdx.x & 31;
    const int wid  = threadIdx.x >> 5;
    if (threadIdx.x == 0) carry = 0;
    __syncthreads();

    for (int base = 0; base < N; base += 1024) {
        int i = base + threadIdx.x;
        int x = (i < N) ? cnt[i] : 0;
        int v = x;
#pragma unroll
        for (int o = 1; o < 32; o <<= 1) {
            int t = __shfl_up_sync(0xffffffffu, v, o);
            if (lane >= o) v += t;
        }
        if (lane == 31) wsum[wid] = v;
        __syncthreads();
        if (wid == 0) {
            int w = wsum[lane];
#pragma unroll
            for (int o = 1; o < 32; o <<= 1) {
                int t = __shfl_up_sync(0xffffffffu, w, o);
                if (lane >= o) w += t;
            }
            wsum[lane] = w;
        }
        __syncthreads();
        int woff = wid ? wsum[wid - 1] : 0;
        if (i < N) off[i] = carry + woff + v - x;   // exclusive prefix
        __syncthreads();
        if (threadIdx.x == 0) carry += wsum[31];
        __syncthreads();
    }
    if (threadIdx.x == 0) off[N] = carry;
}

__global__ void copy_kernel(int* __restrict__ dst, const int* __restrict__ src, int n) {
    int i = blockIdx.x * blockDim.x + threadIdx.x;
    if (i < n) dst[i] = src[i];
}

__global__ void fill_kernel(const void* __restrict__ edges, int E,
                            int* __restrict__ cur, int* __restrict__ srcs) {
    int e = blockIdx.x * blockDim.x + threadIdx.x;
    if (e < E) {
        int dst = load_edge(edges, e);       // edges[0][e]
        int src = load_edge(edges, E + e);   // edges[1][e]
        int pos = atomicAdd(&cur[dst], 1);
        srcs[pos] = src;
    }
}

// ---------------------------------------------------------------------------
// Fused per-node edge attention (flash-style online softmax).
// One block per node; warp h handles head h; lane d handles dimension d.
// ---------------------------------------------------------------------------
__global__ __launch_bounds__(256)
void attn_kernel(const float* __restrict__ q, const float* __restrict__ k,
                 const float* __restrict__ v, const int* __restrict__ off,
                 const int* __restrict__ srcs, float* __restrict__ mid) {
    const int n    = blockIdx.x;
    const int h    = threadIdx.x >> 5;
    const int lane = threadIdx.x & 31;

    const int beg = off[n];
    const int end = off[n + 1];

    const float qv = q[(size_t)n * DM + h * DK + lane];

    float m = -3.4e38f;
    float l = 0.f;
    float acc = 0.f;

    for (int e = beg; e < end; e++) {
        int s = srcs[e];
        const float kd = k[(size_t)s * DM + h * DK + lane];
        const float vd = v[(size_t)s * DM + h * DK + lane];

        float sc = qv * kd;
#pragma unroll
        for (int o = 16; o; o >>= 1)
            sc += __shfl_xor_sync(0xffffffffu, sc, o);
        sc *= 0.17677669529663687f;   // 1/sqrt(32)

        float mn = fmaxf(m, sc);
        float c  = __expf(m - mn);
        float w  = __expf(sc - mn);
        l   = l * c + w;
        acc = acc * c + w * vd;
        m   = mn;
    }

    mid[(size_t)n * DM + h * DK + lane] = (l > 0.f) ? (acc / l) : 0.f;
}

// ---------------------------------------------------------------------------
// Launch
// ---------------------------------------------------------------------------
extern "C" void kernel_launch(void* const* d_in, const int* in_sizes, int n_in,
                              void* d_out, int out_size) {
    const float* query = (const float*)d_in[0];
    const float* key   = (const float*)d_in[1];
    const float* value = (const float*)d_in[2];
    const void*  edges = d_in[3];
    const float* Wq = (const float*)d_in[4];
    const float* bq = (const float*)d_in[5];
    const float* Wk = (const float*)d_in[6];
    const float* bk = (const float*)d_in[7];
    const float* Wv = (const float*)d_in[8];
    const float* bv = (const float*)d_in[9];
    const float* Wo = (const float*)d_in[10];
    const float* bo = (const float*)d_in[11];
    float* out = (float*)d_out;

    int N = in_sizes[0] / DM;
    int E = in_sizes[3] / 2;
    if (N > NN) N = NN;
    if (E > EE) E = EE;

    float *q, *k, *v, *mid;
    int *cnt, *off, *cur, *src;
    cudaGetSymbolAddress((void**)&q,   g_q);
    cudaGetSymbolAddress((void**)&k,   g_k);
    cudaGetSymbolAddress((void**)&v,   g_v);
    cudaGetSymbolAddress((void**)&mid, g_mid);
    cudaGetSymbolAddress((void**)&cnt, g_cnt);
    cudaGetSymbolAddress((void**)&off, g_off);
    cudaGetSymbolAddress((void**)&cur, g_cur);
    cudaGetSymbolAddress((void**)&src, g_src);

    dim3 gemmGrid((N + 127) / 128, DM / 128);

    // Edge dtype detection (device-side, no sync)
    detect_kernel<<<1, 256>>>((const int*)edges);

    // Projections
    sgemm_nt<<<gemmGrid, 256>>>(query, Wq, bq, q, N);
    sgemm_nt<<<gemmGrid, 256>>>(key,   Wk, bk, k, N);
    sgemm_nt<<<gemmGrid, 256>>>(value, Wv, bv, v, N);

    // CSR build by destination node
    zero_kernel<<<(N + 255) / 256, 256>>>(cnt, N);
    degree_kernel<<<(E + 255) / 256, 256>>>(edges, E, cnt);
    scan_kernel<<<1, 1024>>>(cnt, off, N);
    copy_kernel<<<(N + 255) / 256, 256>>>(cur, off, N);
    fill_kernel<<<(E + 255) / 256, 256>>>(edges, E, cur, src);

    // Fused segment softmax + weighted aggregation
    attn_kernel<<<N, 256>>>(q, k, v, off, src, mid);

    // Output projection
    sgemm_nt<<<gemmGrid, 256>>>(mid, Wo, bo, out, N);
}

// round 7
// speedup vs baseline: 1.0001x; 1.0001x over previous
#include <cuda_runtime.h>
#include <math.h>

// Problem constants (fixed by the dataset)
#define NN 50000      // nodes
#define EE 500000     // edges
#define DM 256        // d_model
#define NH 8          // heads
#define DK 32         // d_k

// ---------------------------------------------------------------------------
// Scratch (device globals — no runtime allocation allowed)
// ---------------------------------------------------------------------------
__device__ float g_q[(size_t)NN * DM];
__device__ float g_k[(size_t)NN * DM];
__device__ float g_v[(size_t)NN * DM];
__device__ float g_mid[(size_t)NN * DM];
__device__ int   g_cnt[NN];
__device__ int   g_off[NN + 1];
__device__ int   g_cur[NN];
__device__ int   g_src[EE];
__device__ int   g_is64;   // 1 if edges buffer is int64, 0 if int32

// ---------------------------------------------------------------------------
// Packed f32x2 helpers (sm_103a: FFMA2 doubles fp32 FMA throughput vs
// scalar FFMA-3reg which is half-rate rt_SMSP=2)
// ---------------------------------------------------------------------------
__device__ __forceinline__ unsigned long long ffma2(unsigned long long a,
                                                    unsigned long long b,
                                                    unsigned long long c) {
    unsigned long long d;
    asm("fma.rn.f32x2 %0, %1, %2, %3;" : "=l"(d) : "l"(a), "l"(b), "l"(c));
    return d;
}
__device__ __forceinline__ unsigned long long pack2(float x) {
    unsigned long long d;
    asm("mov.b64 %0, {%1, %1};" : "=l"(d) : "f"(x));
    return d;
}
__device__ __forceinline__ void unpack2(unsigned long long p, float& lo, float& hi) {
    asm("mov.b64 {%0, %1}, %2;" : "=f"(lo), "=f"(hi) : "l"(p));
}

// ---------------------------------------------------------------------------
// Edge index dtype detection: jax may have canonicalized int64 -> int32.
// ---------------------------------------------------------------------------
__global__ void detect_kernel(const int* __restrict__ raw) {
    __shared__ int nz;
    if (threadIdx.x == 0) nz = 0;
    __syncthreads();
    int v = raw[2 * threadIdx.x + 1];
    if (v != 0) atomicAdd(&nz, 1);
    __syncthreads();
    if (threadIdx.x == 0) g_is64 = (nz == 0) ? 1 : 0;
}

__device__ __forceinline__ int load_edge(const void* edges, int idx) {
    if (g_is64) return (int)((const long long*)edges)[idx];
    return ((const int*)edges)[idx];
}

// ---------------------------------------------------------------------------
// SGEMM (NT): C[M,256] = X[M,256] @ W[256,256]^T + bias
// BM=BN=128, BK=8, 256 threads, 8x8 micro-tile per thread.
// Inner product via packed fma.rn.f32x2 (FFMA2) -> 32 packed FMAs per k-step.
// ---------------------------------------------------------------------------
__global__ __launch_bounds__(256, 2)
void sgemm_nt(const float* __restrict__ X, const float* __restrict__ W,
              const float* __restrict__ bias, float* __restrict__ C, int M) {
    __shared__ float As[8][128];
    __shared__ float Bs[8][128];

    const int tid = threadIdx.x;
    const int tx  = tid & 15;     // 0..15 -> 8 output cols each
    const int ty  = tid >> 4;     // 0..15 -> 8 output rows each
    const int rowBase = blockIdx.x * 128;
    const int colBase = blockIdx.y * 128;

    const int lr = tid >> 1;          // 0..127  tile row / weight row
    const int lk = (tid & 1) * 4;     // 0 or 4  k offset within BK

    // accumulators: 8 rows x 4 packed col-pairs (pairs of adjacent columns)
    unsigned long long acc2[8][4];
#pragma unroll
    for (int i = 0; i < 8; i++)
#pragma unroll
        for (int j = 0; j < 4; j++) acc2[i][j] = 0ull;

    const int gr = rowBase + lr;
    const bool rok = (gr < M);
    const float* Xp = X + (size_t)gr * DM + lk;
    const float* Wp = W + (size_t)(colBase + lr) * DM + lk;

    for (int k0 = 0; k0 < DM; k0 += 8) {
        float4 a4 = rok ? *(const float4*)(Xp + k0) : make_float4(0.f, 0.f, 0.f, 0.f);
        float4 b4 = *(const float4*)(Wp + k0);
        As[lk + 0][lr] = a4.x; As[lk + 1][lr] = a4.y;
        As[lk + 2][lr] = a4.z; As[lk + 3][lr] = a4.w;
        Bs[lk + 0][lr] = b4.x; Bs[lk + 1][lr] = b4.y;
        Bs[lk + 2][lr] = b4.z; Bs[lk + 3][lr] = b4.w;
        __syncthreads();

#pragma unroll
        for (int kk = 0; kk < 8; kk++) {
            float a[8];
            *(float4*)&a[0] = *(const float4*)&As[kk][ty * 8];
            *(float4*)&a[4] = *(const float4*)&As[kk][ty * 8 + 4];
            // 8 adjacent B columns as 4 packed f32x2 pairs (32B-aligned)
            ulonglong2 b01 = *(const ulonglong2*)&Bs[kk][tx * 8];
            ulonglong2 b23 = *(const ulonglong2*)&Bs[kk][tx * 8 + 4];
            unsigned long long b2[4];
            b2[0] = b01.x; b2[1] = b01.y; b2[2] = b23.x; b2[3] = b23.y;
#pragma unroll
            for (int i = 0; i < 8; i++) {
                unsigned long long a2 = pack2(a[i]);   // ALU pipe, overlaps FMA
#pragma unroll
                for (int j = 0; j < 4; j++)
                    acc2[i][j] = ffma2(a2, b2[j], acc2[i][j]);
            }
        }
        __syncthreads();
    }

    float bvv[8];
#pragma unroll
    for (int j = 0; j < 8; j++) bvv[j] = bias[colBase + tx * 8 + j];

#pragma unroll
    for (int i = 0; i < 8; i++) {
        int r = rowBase + ty * 8 + i;
        if (r < M) {
            float* Cp = C + (size_t)r * DM + colBase + tx * 8;
            float o[8];
#pragma unroll
            for (int j = 0; j < 4; j++)
                unpack2(acc2[i][j], o[2 * j], o[2 * j + 1]);
            float4 o0, o1;
            o0.x = o[0] + bvv[0]; o0.y = o[1] + bvv[1];
            o0.z = o[2] + bvv[2]; o0.w = o[3] + bvv[3];
            o1.x = o[4] + bvv[4]; o1.y = o[5] + bvv[5];
            o1.z = o[6] + bvv[6]; o1.w = o[7] + bvv[7];
            *(float4*)(Cp + 0) = o0;
            *(float4*)(Cp + 4) = o1;
        }
    }
}

// ---------------------------------------------------------------------------
// CSR build: histogram -> exclusive scan -> fill
// ---------------------------------------------------------------------------
__global__ void zero_kernel(int* __restrict__ p, int n) {
    int i = blockIdx.x * blockDim.x + threadIdx.x;
    if (i < n) p[i] = 0;
}

__global__ void degree_kernel(const void* __restrict__ edges, int E,
                              int* __restrict__ cnt) {
    int e = blockIdx.x * blockDim.x + threadIdx.x;
    if (e < E) {
        int dst = load_edge(edges, e);          // edges[0][e]
        atomicAdd(&cnt[dst], 1);
    }
}

// Single-block exclusive scan over N counts (warp-shuffle based).
__global__ __launch_bounds__(1024)
void scan_kernel(const int* __restrict__ cnt, int* __restrict__ off, int N) {
    __shared__ int wsum[32];
    __shared__ int carry;
    const int lane = threadIdx.x & 31;
    const int wid  = threadIdx.x >> 5;
    if (threadIdx.x == 0) carry = 0;
    __syncthreads();

    for (int base = 0; base < N; base += 1024) {
        int i = base + threadIdx.x;
        int x = (i < N) ? cnt[i] : 0;
        int v = x;
#pragma unroll
        for (int o = 1; o < 32; o <<= 1) {
            int t = __shfl_up_sync(0xffffffffu, v, o);
            if (lane >= o) v += t;
        }
        if (lane == 31) wsum[wid] = v;
        __syncthreads();
        if (wid == 0) {
            int w = wsum[lane];
#pragma unroll
            for (int o = 1; o < 32; o <<= 1) {
                int t = __shfl_up_sync(0xffffffffu, w, o);
                if (lane >= o) w += t;
            }
            wsum[lane] = w;
        }
        __syncthreads();
        int woff = wid ? wsum[wid - 1] : 0;
        if (i < N) off[i] = carry + woff + v - x;   // exclusive prefix
        __syncthreads();
        if (threadIdx.x == 0) carry += wsum[31];
        __syncthreads();
    }
    if (threadIdx.x == 0) off[N] = carry;
}

__global__ void copy_kernel(int* __restrict__ dst, const int* __restrict__ src, int n) {
    int i = blockIdx.x * blockDim.x + threadIdx.x;
    if (i < n) dst[i] = src[i];
}

__global__ void fill_kernel(const void* __restrict__ edges, int E,
                            int* __restrict__ cur, int* __restrict__ srcs) {
    int e = blockIdx.x * blockDim.x + threadIdx.x;
    if (e < E) {
        int dst = load_edge(edges, e);       // edges[0][e]
        int src = load_edge(edges, E + e);   // edges[1][e]
        int pos = atomicAdd(&cur[dst], 1);
        srcs[pos] = src;
    }
}

// ---------------------------------------------------------------------------
// Fused per-node edge attention (flash-style online softmax).
// One block per node; warp h handles head h; lane d handles dimension d.
// 2-edge unroll: independent shuffle-reduce chains hide SHFL latency.
// ---------------------------------------------------------------------------
__device__ __forceinline__ void online_update(float& m, float& l, float& acc,
                                              float sc, float vd) {
    float mn = fmaxf(m, sc);
    float c  = __expf(m - mn);
    float w  = __expf(sc - mn);
    l   = l * c + w;
    acc = acc * c + w * vd;
    m   = mn;
}

__global__ __launch_bounds__(256)
void attn_kernel(const float* __restrict__ q, const float* __restrict__ k,
                 const float* __restrict__ v, const int* __restrict__ off,
                 const int* __restrict__ srcs, float* __restrict__ mid) {
    const int n    = blockIdx.x;
    const int h    = threadIdx.x >> 5;
    const int lane = threadIdx.x & 31;

    const int beg = off[n];
    const int end = off[n + 1];

    const float qv = q[(size_t)n * DM + h * DK + lane];
    const float scale = 0.17677669529663687f;   // 1/sqrt(32)

    float m = -3.4e38f;
    float l = 0.f;
    float acc = 0.f;

    int e = beg;
    for (; e + 1 < end; e += 2) {
        int s0 = srcs[e];
        int s1 = srcs[e + 1];
        float kd0 = k[(size_t)s0 * DM + h * DK + lane];
        float vd0 = v[(size_t)s0 * DM + h * DK + lane];
        float kd1 = k[(size_t)s1 * DM + h * DK + lane];
        float vd1 = v[(size_t)s1 * DM + h * DK + lane];

        float sc0 = qv * kd0;
        float sc1 = qv * kd1;
#pragma unroll
        for (int o = 16; o; o >>= 1) {
            sc0 += __shfl_xor_sync(0xffffffffu, sc0, o);
            sc1 += __shfl_xor_sync(0xffffffffu, sc1, o);
        }
        sc0 *= scale;
        sc1 *= scale;

        online_update(m, l, acc, sc0, vd0);
        online_update(m, l, acc, sc1, vd1);
    }
    if (e < end) {
        int s = srcs[e];
        float kd = k[(size_t)s * DM + h * DK + lane];
        float vd = v[(size_t)s * DM + h * DK + lane];
        float sc = qv * kd;
#pragma unroll
        for (int o = 16; o; o >>= 1)
            sc += __shfl_xor_sync(0xffffffffu, sc, o);
        sc *= scale;
        online_update(m, l, acc, sc, vd);
    }

    mid[(size_t)n * DM + h * DK + lane] = (l > 0.f) ? (acc / l) : 0.f;
}

// ---------------------------------------------------------------------------
// Launch
// ---------------------------------------------------------------------------
extern "C" void kernel_launch(void* const* d_in, const int* in_sizes, int n_in,
                              void* d_out, int out_size) {
    const float* query = (const float*)d_in[0];
    const float* key   = (const float*)d_in[1];
    const float* value = (const float*)d_in[2];
    const void*  edges = d_in[3];
    const float* Wq = (const float*)d_in[4];
    const float* bq = (const float*)d_in[5];
    const float* Wk = (const float*)d_in[6];
    const float* bk = (const float*)d_in[7];
    const float* Wv = (const float*)d_in[8];
    const float* bv = (const float*)d_in[9];
    const float* Wo = (const float*)d_in[10];
    const float* bo = (const float*)d_in[11];
    float* out = (float*)d_out;

    int N = in_sizes[0] / DM;
    int E = in_sizes[3] / 2;
    if (N > NN) N = NN;
    if (E > EE) E = EE;

    float *q, *k, *v, *mid;
    int *cnt, *off, *cur, *src;
    cudaGetSymbolAddress((void**)&q,   g_q);
    cudaGetSymbolAddress((void**)&k,   g_k);
    cudaGetSymbolAddress((void**)&v,   g_v);
    cudaGetSymbolAddress((void**)&mid, g_mid);
    cudaGetSymbolAddress((void**)&cnt, g_cnt);
    cudaGetSymbolAddress((void**)&off, g_off);
    cudaGetSymbolAddress((void**)&cur, g_cur);
    cudaGetSymbolAddress((void**)&src, g_src);

    dim3 gemmGrid((N + 127) / 128, DM / 128);

    // Edge dtype detection (device-side, no sync)
    detect_kernel<<<1, 256>>>((const int*)edges);

    // Projections
    sgemm_nt<<<gemmGrid, 256>>>(query, Wq, bq, q, N);
    sgemm_nt<<<gemmGrid, 256>>>(key,   Wk, bk, k, N);
    sgemm_nt<<<gemmGrid, 256>>>(value, Wv, bv, v, N);

    // CSR build by destination node
    zero_kernel<<<(N + 255) / 256, 256>>>(cnt, N);
    degree_kernel<<<(E + 255) / 256, 256>>>(edges, E, cnt);
    scan_kernel<<<1, 1024>>>(cnt, off, N);
    copy_kernel<<<(N + 255) / 256, 256>>>(cur, off, N);
    fill_kernel<<<(E + 255) / 256, 256>>>(edges, E, cur, src);

    // Fused segment softmax + weighted aggregation
    attn_kernel<<<N, 256>>>(q, k, v, off, src, mid);

    // Output projection
    sgemm_nt<<<gemmGrid, 256>>>(mid, Wo, bo, out, N);
}

// round 14
// speedup vs baseline: 1.8933x; 1.8931x over previous
#include <cuda_runtime.h>
#include <cuda_bf16.h>
#include <math.h>
#include <stdint.h>

// Problem constants (fixed by the dataset)
#define NN 50000      // nodes
#define EE 500000     // edges
#define DM 256        // d_model
#define NH 8          // heads
#define DK 32         // d_k

// ---------------------------------------------------------------------------
// Scratch (device globals — no runtime allocation allowed)
// ---------------------------------------------------------------------------
__device__ float g_q[(size_t)NN * DM];
__device__ float g_k[(size_t)NN * DM];
__device__ float g_v[(size_t)NN * DM];
__device__ float g_mid[(size_t)NN * DM];
__device__ int   g_cnt[NN];
__device__ int   g_off[NN + 1];
__device__ int   g_cur[NN];
__device__ int   g_src[EE];
__device__ int   g_is64;   // 1 if edges buffer is int64, 0 if int32

// ---------------------------------------------------------------------------
// Edge index dtype detection (jax may canonicalize int64 -> int32)
// ---------------------------------------------------------------------------
__global__ void detect_kernel(const int* __restrict__ raw) {
    __shared__ int nz;
    if (threadIdx.x == 0) nz = 0;
    __syncthreads();
    int v = raw[2 * threadIdx.x + 1];
    if (v != 0) atomicAdd(&nz, 1);
    __syncthreads();
    if (threadIdx.x == 0) g_is64 = (nz == 0) ? 1 : 0;
}

__device__ __forceinline__ int load_edge(const void* edges, int idx) {
    if (g_is64) return (int)((const long long*)edges)[idx];
    return ((const int*)edges)[idx];
}

// ---------------------------------------------------------------------------
// mma.sync helpers (sm_80-era PTX; compiles for plain sm_103 target)
// ---------------------------------------------------------------------------
__device__ __forceinline__ uint32_t smem_u32(const void* p) {
    uint32_t a;
    asm("{ .reg .u64 t; cvta.to.shared.u64 t, %1; cvt.u32.u64 %0, t; }"
        : "=r"(a) : "l"(p));
    return a;
}

__device__ __forceinline__ void ldm_x4(uint32_t addr, uint32_t& r0, uint32_t& r1,
                                       uint32_t& r2, uint32_t& r3) {
    asm volatile("ldmatrix.sync.aligned.m8n8.x4.shared.b16 {%0,%1,%2,%3}, [%4];"
                 : "=r"(r0), "=r"(r1), "=r"(r2), "=r"(r3) : "r"(addr));
}

__device__ __forceinline__ void mma16816(float* d, const uint32_t* a,
                                         const uint32_t* b) {
    asm volatile(
        "mma.sync.aligned.m16n8k16.row.col.f32.bf16.bf16.f32 "
        "{%0,%1,%2,%3}, {%4,%5,%6,%7}, {%8,%9}, {%0,%1,%2,%3};"
        : "+f"(d[0]), "+f"(d[1]), "+f"(d[2]), "+f"(d[3])
        : "r"(a[0]), "r"(a[1]), "r"(a[2]), "r"(a[3]), "r"(b[0]), "r"(b[1]));
}

// pack two floats to bf16x2 (low half = first arg)
__device__ __forceinline__ uint32_t pack_bf16(float lo, float hi) {
    uint32_t r;
    asm("cvt.rn.bf16x2.f32 %0, %1, %2;" : "=r"(r) : "f"(hi), "f"(lo));
    return r;
}

// ---------------------------------------------------------------------------
// Tensor-core GEMM (NT): C[M,256] = X[M,256] @ W[256,256]^T + bias
// Split-bf16: X = Xhi+Xlo, W = Whi+Wlo; D = XhiWhi + XhiWlo + XloWhi
// fp32 register accumulation via mma.sync m16n8k16.
// Block 128x128, 256 thr (8 warps x 64x32), K-chunk 32, stride-80 smem pad.
//
// Lane->address mappings for ldmatrix.x4 (DIFFERENT for A and B!):
//   A frag (a0..a3 = [r0-7,k0-7],[r8-15,k0-7],[r0-7,k8-15],[r8-15,k8-15]):
//       row = lane&15,                khalf = lane>>4
//   B frag x4 (b[nt0]{k0,k8}, b[nt1]{k0,k8}):
//       row = (lane&7)+((lane>>4)&1)*8, khalf = (lane>>3)&1
// ---------------------------------------------------------------------------
#define BM 128
#define BN 128
#define BK 32
#define RS 80                 // smem row stride in bytes (conflict-free)
#define TILE_B (128 * RS)     // 10240 bytes per tile
#define A_HI 0
#define A_LO (1 * TILE_B)
#define B_HI (2 * TILE_B)
#define B_LO (3 * TILE_B)

__global__ __launch_bounds__(256, 2)
void gemm_mma(const float* __restrict__ X, const float* __restrict__ W,
              const float* __restrict__ bias, float* __restrict__ C, int M) {
    __shared__ char sm[4 * TILE_B];   // 40960 B (static, <48K)
    const uint32_t sb = smem_u32(sm);

    const int tid  = threadIdx.x;
    const int wid  = tid >> 5;
    const int lane = tid & 31;
    const int warp_m = wid >> 2;          // 0..1  (64 rows each)
    const int warp_n = wid & 3;           // 0..3  (32 cols each)
    const int rowBase = blockIdx.x * BM;
    const int colBase = blockIdx.y * BN;

    // A-operand ldmatrix lane offset
    const uint32_t aoff = (uint32_t)((lane & 15) * RS + (lane >> 4) * 16);
    // B-operand ldmatrix lane offset
    const uint32_t boff = (uint32_t)(((lane & 7) + ((lane >> 4) & 1) * 8) * RS +
                                     ((lane >> 3) & 1) * 16);

    float acc[4][4][4];                   // [mt][nt][frag]
#pragma unroll
    for (int i = 0; i < 4; i++)
#pragma unroll
        for (int j = 0; j < 4; j++)
#pragma unroll
            for (int f = 0; f < 4; f++) acc[i][j][f] = 0.f;

    for (int ch = 0; ch < DM / BK; ch++) {
        const int kc = ch * BK;
        __syncthreads();                  // smem reuse barrier

        // ---- load + split-convert A (128x32) and B (128x32) ----
#pragma unroll
        for (int i = 0; i < 4; i++) {
            int idx = tid + i * 256;      // 0..1023
            int r = idx >> 3, c4 = idx & 7;
            // A
            int gr = rowBase + r;
            float4 x = make_float4(0.f, 0.f, 0.f, 0.f);
            if (gr < M) x = *(const float4*)(X + (size_t)gr * DM + kc + c4 * 4);
            __nv_bfloat16 h0 = __float2bfloat16_rn(x.x);
            __nv_bfloat16 h1 = __float2bfloat16_rn(x.y);
            __nv_bfloat16 h2 = __float2bfloat16_rn(x.z);
            __nv_bfloat16 h3 = __float2bfloat16_rn(x.w);
            uint32_t hi01 = ((uint32_t)__bfloat16_as_ushort(h1) << 16) |
                            (uint32_t)__bfloat16_as_ushort(h0);
            uint32_t hi23 = ((uint32_t)__bfloat16_as_ushort(h3) << 16) |
                            (uint32_t)__bfloat16_as_ushort(h2);
            uint32_t lo01 = pack_bf16(x.x - __bfloat162float(h0),
                                      x.y - __bfloat162float(h1));
            uint32_t lo23 = pack_bf16(x.z - __bfloat162float(h2),
                                      x.w - __bfloat162float(h3));
            *(uint2*)(sm + A_HI + r * RS + c4 * 8) = make_uint2(hi01, hi23);
            *(uint2*)(sm + A_LO + r * RS + c4 * 8) = make_uint2(lo01, lo23);
            // B (weights: rows are output cols; always in-bounds)
            int gn = colBase + r;
            float4 w = *(const float4*)(W + (size_t)gn * DM + kc + c4 * 4);
            __nv_bfloat16 w0 = __float2bfloat16_rn(w.x);
            __nv_bfloat16 w1 = __float2bfloat16_rn(w.y);
            __nv_bfloat16 w2 = __float2bfloat16_rn(w.z);
            __nv_bfloat16 w3 = __float2bfloat16_rn(w.w);
            uint32_t whi01 = ((uint32_t)__bfloat16_as_ushort(w1) << 16) |
                             (uint32_t)__bfloat16_as_ushort(w0);
            uint32_t whi23 = ((uint32_t)__bfloat16_as_ushort(w3) << 16) |
                             (uint32_t)__bfloat16_as_ushort(w2);
            uint32_t wlo01 = pack_bf16(w.x - __bfloat162float(w0),
                                       w.y - __bfloat162float(w1));
            uint32_t wlo23 = pack_bf16(w.z - __bfloat162float(w2),
                                       w.w - __bfloat162float(w3));
            *(uint2*)(sm + B_HI + r * RS + c4 * 8) = make_uint2(whi01, whi23);
            *(uint2*)(sm + B_LO + r * RS + c4 * 8) = make_uint2(wlo01, wlo23);
        }
        __syncthreads();

        // ---- MMA over the chunk: 2 k16 steps ----
#pragma unroll
        for (int ks = 0; ks < 2; ks++) {
            const uint32_t kstep = (uint32_t)(ks * 32);   // 16 bf16 = 32 bytes
            uint32_t bh[4][2], bl[4][2];
#pragma unroll
            for (int p = 0; p < 2; p++) {   // nt pair: covers nt=2p, 2p+1
                uint32_t ba = sb + (uint32_t)((warp_n * 32 + p * 16) * RS) +
                              kstep + boff;
                ldm_x4(ba + B_HI, bh[2 * p][0], bh[2 * p][1],
                                   bh[2 * p + 1][0], bh[2 * p + 1][1]);
                ldm_x4(ba + B_LO, bl[2 * p][0], bl[2 * p][1],
                                   bl[2 * p + 1][0], bl[2 * p + 1][1]);
            }
#pragma unroll
            for (int mt = 0; mt < 4; mt++) {
                uint32_t aa = sb + (uint32_t)((warp_m * 64 + mt * 16) * RS) +
                              kstep + aoff;
                uint32_t ah[4], al[4];
                ldm_x4(aa + A_HI, ah[0], ah[1], ah[2], ah[3]);
                ldm_x4(aa + A_LO, al[0], al[1], al[2], al[3]);
#pragma unroll
                for (int nt = 0; nt < 4; nt++) {
                    mma16816(acc[mt][nt], ah, bh[nt]);
                    mma16816(acc[mt][nt], ah, bl[nt]);
                    mma16816(acc[mt][nt], al, bh[nt]);
                }
            }
        }
    }

    // ---- Epilogue: acc + bias -> C ----
    const int r0 = lane >> 2;
    const int qc = (lane & 3) * 2;
#pragma unroll
    for (int nt = 0; nt < 4; nt++) {
        int gc = colBase + warp_n * 32 + nt * 8 + qc;
        float2 bb = *(const float2*)(bias + gc);
#pragma unroll
        for (int mt = 0; mt < 4; mt++) {
            int gr0 = rowBase + warp_m * 64 + mt * 16 + r0;
            if (gr0 < M) {
                float2 o = make_float2(acc[mt][nt][0] + bb.x,
                                       acc[mt][nt][1] + bb.y);
                *(float2*)(C + (size_t)gr0 * DM + gc) = o;
            }
            int gr1 = gr0 + 8;
            if (gr1 < M) {
                float2 o = make_float2(acc[mt][nt][2] + bb.x,
                                       acc[mt][nt][3] + bb.y);
                *(float2*)(C + (size_t)gr1 * DM + gc) = o;
            }
        }
    }
}

// ---------------------------------------------------------------------------
// CSR build: histogram -> exclusive scan -> fill
// ---------------------------------------------------------------------------
__global__ void zero_kernel(int* __restrict__ p, int n) {
    int i = blockIdx.x * blockDim.x + threadIdx.x;
    if (i < n) p[i] = 0;
}

__global__ void degree_kernel(const void* __restrict__ edges, int E,
                              int* __restrict__ cnt) {
    int e = blockIdx.x * blockDim.x + threadIdx.x;
    if (e < E) {
        int dst = load_edge(edges, e);
        atomicAdd(&cnt[dst], 1);
    }
}

__global__ __launch_bounds__(1024)
void scan_kernel(const int* __restrict__ cnt, int* __restrict__ off, int N) {
    __shared__ int wsum[32];
    __shared__ int carry;
    const int lane = threadIdx.x & 31;
    const int wid  = threadIdx.x >> 5;
    if (threadIdx.x == 0) carry = 0;
    __syncthreads();

    for (int base = 0; base < N; base += 1024) {
        int i = base + threadIdx.x;
        int x = (i < N) ? cnt[i] : 0;
        int v = x;
#pragma unroll
        for (int o = 1; o < 32; o <<= 1) {
            int t = __shfl_up_sync(0xffffffffu, v, o);
            if (lane >= o) v += t;
        }
        if (lane == 31) wsum[wid] = v;
        __syncthreads();
        if (wid == 0) {
            int w = wsum[lane];
#pragma unroll
            for (int o = 1; o < 32; o <<= 1) {
                int t = __shfl_up_sync(0xffffffffu, w, o);
                if (lane >= o) w += t;
            }
            wsum[lane] = w;
        }
        __syncthreads();
        int woff = wid ? wsum[wid - 1] : 0;
        if (i < N) off[i] = carry + woff + v - x;
        __syncthreads();
        if (threadIdx.x == 0) carry += wsum[31];
        __syncthreads();
    }
    if (threadIdx.x == 0) off[N] = carry;
}

__global__ void copy_kernel(int* __restrict__ dst, const int* __restrict__ src, int n) {
    int i = blockIdx.x * blockDim.x + threadIdx.x;
    if (i < n) dst[i] = src[i];
}

__global__ void fill_kernel(const void* __restrict__ edges, int E,
                            int* __restrict__ cur, int* __restrict__ srcs) {
    int e = blockIdx.x * blockDim.x + threadIdx.x;
    if (e < E) {
        int dst = load_edge(edges, e);
        int src = load_edge(edges, E + e);
        int pos = atomicAdd(&cur[dst], 1);
        srcs[pos] = src;
    }
}

// ---------------------------------------------------------------------------
// Fused per-node edge attention (flash-style online softmax).
// ---------------------------------------------------------------------------
__device__ __forceinline__ void online_update(float& m, float& l, float& acc,
                                              float sc, float vd) {
    float mn = fmaxf(m, sc);
    float c  = __expf(m - mn);
    float w  = __expf(sc - mn);
    l   = l * c + w;
    acc = acc * c + w * vd;
    m   = mn;
}

__global__ __launch_bounds__(256)
void attn_kernel(const float* __restrict__ q, const float* __restrict__ k,
                 const float* __restrict__ v, const int* __restrict__ off,
                 const int* __restrict__ srcs, float* __restrict__ mid) {
    const int n    = blockIdx.x;
    const int h    = threadIdx.x >> 5;
    const int lane = threadIdx.x & 31;

    const int beg = off[n];
    const int end = off[n + 1];

    const float qv = q[(size_t)n * DM + h * DK + lane];
    const float scale = 0.17677669529663687f;   // 1/sqrt(32)

    float m = -3.4e38f;
    float l = 0.f;
    float acc = 0.f;

    int e = beg;
    for (; e + 1 < end; e += 2) {
        int s0 = srcs[e];
        int s1 = srcs[e + 1];
        float kd0 = k[(size_t)s0 * DM + h * DK + lane];
        float vd0 = v[(size_t)s0 * DM + h * DK + lane];
        float kd1 = k[(size_t)s1 * DM + h * DK + lane];
        float vd1 = v[(size_t)s1 * DM + h * DK + lane];

        float sc0 = qv * kd0;
        float sc1 = qv * kd1;
#pragma unroll
        for (int o = 16; o; o >>= 1) {
            sc0 += __shfl_xor_sync(0xffffffffu, sc0, o);
            sc1 += __shfl_xor_sync(0xffffffffu, sc1, o);
        }
        sc0 *= scale;
        sc1 *= scale;

        online_update(m, l, acc, sc0, vd0);
        online_update(m, l, acc, sc1, vd1);
    }
    if (e < end) {
        int s = srcs[e];
        float kd = k[(size_t)s * DM + h * DK + lane];
        float vd = v[(size_t)s * DM + h * DK + lane];
        float sc = qv * kd;
#pragma unroll
        for (int o = 16; o; o >>= 1)
            sc += __shfl_xor_sync(0xffffffffu, sc, o);
        sc *= scale;
        online_update(m, l, acc, sc, vd);
    }

    mid[(size_t)n * DM + h * DK + lane] = (l > 0.f) ? (acc / l) : 0.f;
}

// ---------------------------------------------------------------------------
// Launch
// ---------------------------------------------------------------------------
extern "C" void kernel_launch(void* const* d_in, const int* in_sizes, int n_in,
                              void* d_out, int out_size) {
    const float* query = (const float*)d_in[0];
    const float* key   = (const float*)d_in[1];
    const float* value = (const float*)d_in[2];
    const void*  edges = d_in[3];
    const float* Wq = (const float*)d_in[4];
    const float* bq = (const float*)d_in[5];
    const float* Wk = (const float*)d_in[6];
    const float* bk = (const float*)d_in[7];
    const float* Wv = (const float*)d_in[8];
    const float* bv = (const float*)d_in[9];
    const float* Wo = (const float*)d_in[10];
    const float* bo = (const float*)d_in[11];
    float* out = (float*)d_out;

    int N = in_sizes[0] / DM;
    int E = in_sizes[3] / 2;
    if (N > NN) N = NN;
    if (E > EE) E = EE;

    float *q, *k, *v, *mid;
    int *cnt, *off, *cur, *src;
    cudaGetSymbolAddress((void**)&q,   g_q);
    cudaGetSymbolAddress((void**)&k,   g_k);
    cudaGetSymbolAddress((void**)&v,   g_v);
    cudaGetSymbolAddress((void**)&mid, g_mid);
    cudaGetSymbolAddress((void**)&cnt, g_cnt);
    cudaGetSymbolAddress((void**)&off, g_off);
    cudaGetSymbolAddress((void**)&cur, g_cur);
    cudaGetSymbolAddress((void**)&src, g_src);

    dim3 gemmGrid((N + BM - 1) / BM, DM / BN);

    // Edge dtype detection (device-side, no sync)
    detect_kernel<<<1, 256>>>((const int*)edges);

    // Projections (tensor cores via mma.sync, split-bf16)
    gemm_mma<<<gemmGrid, 256>>>(query, Wq, bq, q, N);
    gemm_mma<<<gemmGrid, 256>>>(key,   Wk, bk, k, N);
    gemm_mma<<<gemmGrid, 256>>>(value, Wv, bv, v, N);

    // CSR build by destination node
    zero_kernel<<<(N + 255) / 256, 256>>>(cnt, N);
    degree_kernel<<<(E + 255) / 256, 256>>>(edges, E, cnt);
    scan_kernel<<<1, 1024>>>(cnt, off, N);
    copy_kernel<<<(N + 255) / 256, 256>>>(cur, off, N);
    fill_kernel<<<(E + 255) / 256, 256>>>(edges, E, cur, src);

    // Fused segment softmax + weighted aggregation
    attn_kernel<<<N, 256>>>(q, k, v, off, src, mid);

    // Output projection
    gemm_mma<<<gemmGrid, 256>>>(mid, Wo, bo, out, N);
}

// round 17
// speedup vs baseline: 2.2085x; 1.1665x over previous
#include <cuda_runtime.h>
#include <cuda_bf16.h>
#include <math.h>
#include <stdint.h>

// Problem constants (fixed by the dataset)
#define NN 50000      // nodes
#define EE 500000     // edges
#define DM 256        // d_model
#define NH 8          // heads
#define DK 32         // d_k

// ---------------------------------------------------------------------------
// Scratch (device globals — identical footprint to the passing R14 build)
// ---------------------------------------------------------------------------
__device__ float g_q[(size_t)NN * DM];
__device__ float g_k[(size_t)NN * DM];
__device__ float g_v[(size_t)NN * DM];
__device__ float g_mid[(size_t)NN * DM];
__device__ int   g_cnt[NN];
__device__ int   g_off[NN + 1];
__device__ int   g_cur[NN];
__device__ int   g_src[EE];
__device__ int   g_is64;   // 1 if edges buffer is int64, 0 if int32

// ---------------------------------------------------------------------------
// Edge index dtype detection (jax may canonicalize int64 -> int32)
// ---------------------------------------------------------------------------
__global__ void detect_kernel(const int* __restrict__ raw) {
    __shared__ int nz;
    if (threadIdx.x == 0) nz = 0;
    __syncthreads();
    int v = raw[2 * threadIdx.x + 1];
    if (v != 0) atomicAdd(&nz, 1);
    __syncthreads();
    if (threadIdx.x == 0) g_is64 = (nz == 0) ? 1 : 0;
}

__device__ __forceinline__ int load_edge(const void* edges, int idx) {
    if (g_is64) return (int)((const long long*)edges)[idx];
    return ((const int*)edges)[idx];
}

// ---------------------------------------------------------------------------
// mma.sync helpers (sm_80-era PTX; compiles for plain sm_103 target)
// ---------------------------------------------------------------------------
__device__ __forceinline__ uint32_t smem_u32(const void* p) {
    uint32_t a;
    asm("{ .reg .u64 t; cvta.to.shared.u64 t, %1; cvt.u32.u64 %0, t; }"
        : "=r"(a) : "l"(p));
    return a;
}

__device__ __forceinline__ void ldm_x4(uint32_t addr, uint32_t& r0, uint32_t& r1,
                                       uint32_t& r2, uint32_t& r3) {
    asm volatile("ldmatrix.sync.aligned.m8n8.x4.shared.b16 {%0,%1,%2,%3}, [%4];"
                 : "=r"(r0), "=r"(r1), "=r"(r2), "=r"(r3) : "r"(addr));
}

__device__ __forceinline__ void mma16816(float* d, const uint32_t* a,
                                         const uint32_t* b) {
    asm volatile(
        "mma.sync.aligned.m16n8k16.row.col.f32.bf16.bf16.f32 "
        "{%0,%1,%2,%3}, {%4,%5,%6,%7}, {%8,%9}, {%0,%1,%2,%3};"
        : "+f"(d[0]), "+f"(d[1]), "+f"(d[2]), "+f"(d[3])
        : "r"(a[0]), "r"(a[1]), "r"(a[2]), "r"(a[3]), "r"(b[0]), "r"(b[1]));
}

// pack two floats to bf16x2 (low half = first arg)
__device__ __forceinline__ uint32_t pack_bf16(float lo, float hi) {
    uint32_t r;
    asm("cvt.rn.bf16x2.f32 %0, %1, %2;" : "=r"(r) : "f"(hi), "f"(lo));
    return r;
}

// ---------------------------------------------------------------------------
// Tensor-core GEMM (NT): C[M,256] = X[M,256] @ W[256,256]^T + bias
// Split-bf16: X = Xhi+Xlo, W = Whi+Wlo; D = XhiWhi + XhiWlo + XloWhi
// fp32 register accumulation via mma.sync m16n8k16.
// Block 128x128, 256 thr (8 warps x 64x32), K-chunk 32, stride-80 smem pad.
// (Exact R14 configuration — known-passing.)
// ---------------------------------------------------------------------------
#define BM 128
#define BN 128
#define BK 32
#define RS 80                 // smem row stride in bytes (conflict-free)
#define TILE_B (128 * RS)     // 10240 bytes per tile
#define A_HI 0
#define A_LO (1 * TILE_B)
#define B_HI (2 * TILE_B)
#define B_LO (3 * TILE_B)

__global__ __launch_bounds__(256, 2)
void gemm_mma(const float* __restrict__ X, const float* __restrict__ W,
              const float* __restrict__ bias, float* __restrict__ C, int M) {
    __shared__ char sm[4 * TILE_B];   // 40960 B (static, <48K)
    const uint32_t sb = smem_u32(sm);

    const int tid  = threadIdx.x;
    const int wid  = tid >> 5;
    const int lane = tid & 31;
    const int warp_m = wid >> 2;          // 0..1  (64 rows each)
    const int warp_n = wid & 3;           // 0..3  (32 cols each)
    const int rowBase = blockIdx.x * BM;
    const int colBase = blockIdx.y * BN;

    // A-operand ldmatrix lane offset: row = lane&15, khalf = lane>>4
    const uint32_t aoff = (uint32_t)((lane & 15) * RS + (lane >> 4) * 16);
    // B-operand ldmatrix lane offset: row = (lane&7)+((lane>>4)&1)*8,
    //                                 khalf = (lane>>3)&1
    const uint32_t boff = (uint32_t)(((lane & 7) + ((lane >> 4) & 1) * 8) * RS +
                                     ((lane >> 3) & 1) * 16);

    float acc[4][4][4];                   // [mt][nt][frag]
#pragma unroll
    for (int i = 0; i < 4; i++)
#pragma unroll
        for (int j = 0; j < 4; j++)
#pragma unroll
            for (int f = 0; f < 4; f++) acc[i][j][f] = 0.f;

    for (int ch = 0; ch < DM / BK; ch++) {
        const int kc = ch * BK;
        __syncthreads();                  // smem reuse barrier

        // ---- load + split-convert A (128x32) and B (128x32) ----
#pragma unroll
        for (int i = 0; i < 4; i++) {
            int idx = tid + i * 256;      // 0..1023
            int r = idx >> 3, c4 = idx & 7;
            // A
            int gr = rowBase + r;
            float4 x = make_float4(0.f, 0.f, 0.f, 0.f);
            if (gr < M) x = *(const float4*)(X + (size_t)gr * DM + kc + c4 * 4);
            __nv_bfloat16 h0 = __float2bfloat16_rn(x.x);
            __nv_bfloat16 h1 = __float2bfloat16_rn(x.y);
            __nv_bfloat16 h2 = __float2bfloat16_rn(x.z);
            __nv_bfloat16 h3 = __float2bfloat16_rn(x.w);
            uint32_t hi01 = ((uint32_t)__bfloat16_as_ushort(h1) << 16) |
                            (uint32_t)__bfloat16_as_ushort(h0);
            uint32_t hi23 = ((uint32_t)__bfloat16_as_ushort(h3) << 16) |
                            (uint32_t)__bfloat16_as_ushort(h2);
            uint32_t lo01 = pack_bf16(x.x - __bfloat162float(h0),
                                      x.y - __bfloat162float(h1));
            uint32_t lo23 = pack_bf16(x.z - __bfloat162float(h2),
                                      x.w - __bfloat162float(h3));
            *(uint2*)(sm + A_HI + r * RS + c4 * 8) = make_uint2(hi01, hi23);
            *(uint2*)(sm + A_LO + r * RS + c4 * 8) = make_uint2(lo01, lo23);
            // B (weights: rows are output cols; always in-bounds)
            int gn = colBase + r;
            float4 w = *(const float4*)(W + (size_t)gn * DM + kc + c4 * 4);
            __nv_bfloat16 w0 = __float2bfloat16_rn(w.x);
            __nv_bfloat16 w1 = __float2bfloat16_rn(w.y);
            __nv_bfloat16 w2 = __float2bfloat16_rn(w.z);
            __nv_bfloat16 w3 = __float2bfloat16_rn(w.w);
            uint32_t whi01 = ((uint32_t)__bfloat16_as_ushort(w1) << 16) |
                             (uint32_t)__bfloat16_as_ushort(w0);
            uint32_t whi23 = ((uint32_t)__bfloat16_as_ushort(w3) << 16) |
                             (uint32_t)__bfloat16_as_ushort(w2);
            uint32_t wlo01 = pack_bf16(w.x - __bfloat162float(w0),
                                       w.y - __bfloat162float(w1));
            uint32_t wlo23 = pack_bf16(w.z - __bfloat162float(w2),
                                       w.w - __bfloat162float(w3));
            *(uint2*)(sm + B_HI + r * RS + c4 * 8) = make_uint2(whi01, whi23);
            *(uint2*)(sm + B_LO + r * RS + c4 * 8) = make_uint2(wlo01, wlo23);
        }
        __syncthreads();

        // ---- MMA over the chunk: 2 k16 steps ----
#pragma unroll
        for (int ks = 0; ks < 2; ks++) {
            const uint32_t kstep = (uint32_t)(ks * 32);   // 16 bf16 = 32 bytes
            uint32_t bh[4][2], bl[4][2];
#pragma unroll
            for (int p = 0; p < 2; p++) {   // nt pair: covers nt=2p, 2p+1
                uint32_t ba = sb + (uint32_t)((warp_n * 32 + p * 16) * RS) +
                              kstep + boff;
                ldm_x4(ba + B_HI, bh[2 * p][0], bh[2 * p][1],
                                   bh[2 * p + 1][0], bh[2 * p + 1][1]);
                ldm_x4(ba + B_LO, bl[2 * p][0], bl[2 * p][1],
                                   bl[2 * p + 1][0], bl[2 * p + 1][1]);
            }
#pragma unroll
            for (int mt = 0; mt < 4; mt++) {
                uint32_t aa = sb + (uint32_t)((warp_m * 64 + mt * 16) * RS) +
                              kstep + aoff;
                uint32_t ah[4], al[4];
                ldm_x4(aa + A_HI, ah[0], ah[1], ah[2], ah[3]);
                ldm_x4(aa + A_LO, al[0], al[1], al[2], al[3]);
#pragma unroll
                for (int nt = 0; nt < 4; nt++) {
                    mma16816(acc[mt][nt], ah, bh[nt]);
                    mma16816(acc[mt][nt], ah, bl[nt]);
                    mma16816(acc[mt][nt], al, bh[nt]);
                }
            }
        }
    }

    // ---- Epilogue: acc + bias -> C ----
    const int r0 = lane >> 2;
    const int qc = (lane & 3) * 2;
#pragma unroll
    for (int nt = 0; nt < 4; nt++) {
        int gc = colBase + warp_n * 32 + nt * 8 + qc;
        float2 bb = *(const float2*)(bias + gc);
#pragma unroll
        for (int mt = 0; mt < 4; mt++) {
            int gr0 = rowBase + warp_m * 64 + mt * 16 + r0;
            if (gr0 < M) {
                float2 o = make_float2(acc[mt][nt][0] + bb.x,
                                       acc[mt][nt][1] + bb.y);
                *(float2*)(C + (size_t)gr0 * DM + gc) = o;
            }
            int gr1 = gr0 + 8;
            if (gr1 < M) {
                float2 o = make_float2(acc[mt][nt][2] + bb.x,
                                       acc[mt][nt][3] + bb.y);
                *(float2*)(C + (size_t)gr1 * DM + gc) = o;
            }
        }
    }
}

// ---------------------------------------------------------------------------
// CSR build: histogram -> exclusive scan -> fill
// ---------------------------------------------------------------------------
__global__ void zero_kernel(int* __restrict__ p, int n) {
    int i = blockIdx.x * blockDim.x + threadIdx.x;
    if (i < n) p[i] = 0;
}

__global__ void degree_kernel(const void* __restrict__ edges, int E,
                              int* __restrict__ cnt) {
    int e = blockIdx.x * blockDim.x + threadIdx.x;
    if (e < E) {
        int dst = load_edge(edges, e);
        atomicAdd(&cnt[dst], 1);
    }
}

__global__ __launch_bounds__(1024)
void scan_kernel(const int* __restrict__ cnt, int* __restrict__ off, int N) {
    __shared__ int wsum[32];
    __shared__ int carry;
    const int lane = threadIdx.x & 31;
    const int wid  = threadIdx.x >> 5;
    if (threadIdx.x == 0) carry = 0;
    __syncthreads();

    for (int base = 0; base < N; base += 1024) {
        int i = base + threadIdx.x;
        int x = (i < N) ? cnt[i] : 0;
        int v = x;
#pragma unroll
        for (int o = 1; o < 32; o <<= 1) {
            int t = __shfl_up_sync(0xffffffffu, v, o);
            if (lane >= o) v += t;
        }
        if (lane == 31) wsum[wid] = v;
        __syncthreads();
        if (wid == 0) {
            int w = wsum[lane];
#pragma unroll
            for (int o = 1; o < 32; o <<= 1) {
                int t = __shfl_up_sync(0xffffffffu, w, o);
                if (lane >= o) w += t;
            }
            wsum[lane] = w;
        }
        __syncthreads();
        int woff = wid ? wsum[wid - 1] : 0;
        if (i < N) off[i] = carry + woff + v - x;
        __syncthreads();
        if (threadIdx.x == 0) carry += wsum[31];
        __syncthreads();
    }
    if (threadIdx.x == 0) off[N] = carry;
}

__global__ void copy_kernel(int* __restrict__ dst, const int* __restrict__ src, int n) {
    int i = blockIdx.x * blockDim.x + threadIdx.x;
    if (i < n) dst[i] = src[i];
}

__global__ void fill_kernel(const void* __restrict__ edges, int E,
                            int* __restrict__ cur, int* __restrict__ srcs) {
    int e = blockIdx.x * blockDim.x + threadIdx.x;
    if (e < E) {
        int dst = load_edge(edges, e);
        int src = load_edge(edges, E + e);
        int pos = atomicAdd(&cur[dst], 1);
        srcs[pos] = src;
    }
}

// ---------------------------------------------------------------------------
// Fused per-node edge attention (flash-style online softmax).
// 8 lanes per head, float4 per lane: 4 heads/warp, 2 warps/node, 4 nodes/block.
// Shuffle reduce depth 3 (within 8-lane head groups).
// ---------------------------------------------------------------------------
__global__ __launch_bounds__(256)
void attn_kernel(const float* __restrict__ q, const float* __restrict__ k,
                 const float* __restrict__ v, const int* __restrict__ off,
                 const int* __restrict__ srcs, float* __restrict__ mid, int N) {
    const int w    = threadIdx.x >> 5;
    const int lane = threadIdx.x & 31;
    const int n    = blockIdx.x * 4 + (w >> 1);
    if (n >= N) return;

    const int hgrp = (w & 1) * 4;            // heads 0-3 or 4-7
    const int hl   = lane >> 3;              // local head 0..3
    const int d4   = (lane & 7) * 4;         // dim offset within head
    const int col  = (hgrp + hl) * DK + d4;  // column within the 256-wide row

    const int beg = off[n];
    const int end = off[n + 1];

    const float4 qv = *(const float4*)(q + (size_t)n * DM + col);
    const float scale = 0.17677669529663687f;   // 1/sqrt(32)

    float m = -3.4e38f;
    float l = 0.f;
    float4 acc = make_float4(0.f, 0.f, 0.f, 0.f);

    int e = beg;
    for (; e + 1 < end; e += 2) {
        int s0 = srcs[e];
        int s1 = srcs[e + 1];
        const float4 kd0 = *(const float4*)(k + (size_t)s0 * DM + col);
        const float4 vd0 = *(const float4*)(v + (size_t)s0 * DM + col);
        const float4 kd1 = *(const float4*)(k + (size_t)s1 * DM + col);
        const float4 vd1 = *(const float4*)(v + (size_t)s1 * DM + col);

        float sc0 = qv.x * kd0.x + qv.y * kd0.y + qv.z * kd0.z + qv.w * kd0.w;
        float sc1 = qv.x * kd1.x + qv.y * kd1.y + qv.z * kd1.z + qv.w * kd1.w;
#pragma unroll
        for (int o = 4; o; o >>= 1) {
            sc0 += __shfl_xor_sync(0xffffffffu, sc0, o);
            sc1 += __shfl_xor_sync(0xffffffffu, sc1, o);
        }
        sc0 *= scale;
        sc1 *= scale;

        {
            float mn = fmaxf(m, sc0);
            float c  = __expf(m - mn);
            float wt = __expf(sc0 - mn);
            l = l * c + wt;
            acc.x = acc.x * c + wt * vd0.x;
            acc.y = acc.y * c + wt * vd0.y;
            acc.z = acc.z * c + wt * vd0.z;
            acc.w = acc.w * c + wt * vd0.w;
            m = mn;
        }
        {
            float mn = fmaxf(m, sc1);
            float c  = __expf(m - mn);
            float wt = __expf(sc1 - mn);
            l = l * c + wt;
            acc.x = acc.x * c + wt * vd1.x;
            acc.y = acc.y * c + wt * vd1.y;
            acc.z = acc.z * c + wt * vd1.z;
            acc.w = acc.w * c + wt * vd1.w;
            m = mn;
        }
    }
    if (e < end) {
        int s = srcs[e];
        const float4 kd = *(const float4*)(k + (size_t)s * DM + col);
        const float4 vd = *(const float4*)(v + (size_t)s * DM + col);
        float sc = qv.x * kd.x + qv.y * kd.y + qv.z * kd.z + qv.w * kd.w;
#pragma unroll
        for (int o = 4; o; o >>= 1)
            sc += __shfl_xor_sync(0xffffffffu, sc, o);
        sc *= scale;
        float mn = fmaxf(m, sc);
        float c  = __expf(m - mn);
        float wt = __expf(sc - mn);
        l = l * c + wt;
        acc.x = acc.x * c + wt * vd.x;
        acc.y = acc.y * c + wt * vd.y;
        acc.z = acc.z * c + wt * vd.z;
        acc.w = acc.w * c + wt * vd.w;
        m = mn;
    }

    float inv = (l > 0.f) ? (1.f / l) : 0.f;
    float4 o = make_float4(acc.x * inv, acc.y * inv, acc.z * inv, acc.w * inv);
    *(float4*)(mid + (size_t)n * DM + col) = o;
}

// ---------------------------------------------------------------------------
// Launch
// ---------------------------------------------------------------------------
extern "C" void kernel_launch(void* const* d_in, const int* in_sizes, int n_in,
                              void* d_out, int out_size) {
    const float* query = (const float*)d_in[0];
    const float* key   = (const float*)d_in[1];
    const float* value = (const float*)d_in[2];
    const void*  edges = d_in[3];
    const float* Wq = (const float*)d_in[4];
    const float* bq = (const float*)d_in[5];
    const float* Wk = (const float*)d_in[6];
    const float* bk = (const float*)d_in[7];
    const float* Wv = (const float*)d_in[8];
    const float* bv = (const float*)d_in[9];
    const float* Wo = (const float*)d_in[10];
    const float* bo = (const float*)d_in[11];
    float* out = (float*)d_out;

    int N = in_sizes[0] / DM;
    int E = in_sizes[3] / 2;
    if (N > NN) N = NN;
    if (E > EE) E = EE;

    float *q, *k, *v, *mid;
    int *cnt, *off, *cur, *src;
    cudaGetSymbolAddress((void**)&q,   g_q);
    cudaGetSymbolAddress((void**)&k,   g_k);
    cudaGetSymbolAddress((void**)&v,   g_v);
    cudaGetSymbolAddress((void**)&mid, g_mid);
    cudaGetSymbolAddress((void**)&cnt, g_cnt);
    cudaGetSymbolAddress((void**)&off, g_off);
    cudaGetSymbolAddress((void**)&cur, g_cur);
    cudaGetSymbolAddress((void**)&src, g_src);

    dim3 gemmGrid((N + BM - 1) / BM, DM / BN);

    // Edge dtype detection (device-side, no sync)
    detect_kernel<<<1, 256>>>((const int*)edges);

    // Projections (tensor cores via mma.sync, split-bf16)
    gemm_mma<<<gemmGrid, 256>>>(query, Wq, bq, q, N);
    gemm_mma<<<gemmGrid, 256>>>(key,   Wk, bk, k, N);
    gemm_mma<<<gemmGrid, 256>>>(value, Wv, bv, v, N);

    // CSR build by destination node
    zero_kernel<<<(N + 255) / 256, 256>>>(cnt, N);
    degree_kernel<<<(E + 255) / 256, 256>>>(edges, E, cnt);
    scan_kernel<<<1, 1024>>>(cnt, off, N);
    copy_kernel<<<(N + 255) / 256, 256>>>(cur, off, N);
    fill_kernel<<<(E + 255) / 256, 256>>>(edges, E, cur, src);

    // Fused segment softmax + weighted aggregation (new layout)
    attn_kernel<<<(N + 3) / 4, 256>>>(q, k, v, off, src, mid, N);

    // Output projection
    gemm_mma<<<gemmGrid, 256>>>(mid, Wo, bo, out, N);
}